// round 4
// baseline (speedup 1.0000x reference)
#include <cuda_runtime.h>
#include <mma.h>
#include <math.h>

using namespace nvcuda;

#define BSZ 8
#define TD  64
#define TE  512
#define HH  512

// Scratch (allocation-free rule: __device__ globals)
__device__ float g_u  [BSZ*TD*HH];
__device__ float g_Eu [BSZ*TD*HH];
__device__ float g_v  [BSZ*TE*HH];
__device__ float g_Ev [BSZ*TE*HH];
__device__ float g_S1 [BSZ*HH];
__device__ float g_S2 [BSZ*HH];
__device__ float g_lse[BSZ*TD*TE];

__device__ __forceinline__ void cvt_hl(float x, float& h, float& l) {
    h = wmma::__float_to_tf32(x);
    l = wmma::__float_to_tf32(x - h);   // x-h exact in fp32
}

// ---------------------------------------------------------------------------
// Batched GEMM on tensor cores, split-TF32 (hi/lo) for ~fp32 accuracy.
//   BROW=false : C = A @ B^T   (A [M,K] row-major, B [N,K] row-major)
//   BROW=true  : C = A @ B     (B [K,N] row-major)
// 64x64 CTA tile, BK=16, 128 threads (4 warps, each 32x32 of C).
// MODE 0: C1 = acc + bias[col]; C2 = exp(C1)        (u, Eu)
// MODE 1: C1 = acc;             C2 = exp(acc)       (v, Ev)
// MODE 2: C1 = log(acc)                              (lse, no shift needed)
// MODE 3: C1 = uu*S1[d] + S2[d] - acc                (final context)
// ---------------------------------------------------------------------------
template<int MODE, bool BROW>
__global__ void __launch_bounds__(128) gemm_tf32(
    const float* __restrict__ Abase, int lda, long sA,
    const float* __restrict__ Bbase, int ldb, long sB,
    float* __restrict__ C1, float* __restrict__ C2, int ldc, long sC,
    int K,
    const float* __restrict__ bias,
    const float* __restrict__ uu,
    const float* __restrict__ S1,
    const float* __restrict__ S2)
{
    __shared__ float Ah[64*16], Al[64*16];
    __shared__ float Bh[64*16], Bl[64*16];
    __shared__ float Cs[64*64];

    const int b   = blockIdx.z;
    const int tid = threadIdx.x;
    const float* A = Abase + (long)b * sA + (long)blockIdx.y * 64 * lda;
    const float* Bm = BROW
        ? Bbase + (long)b * sB + blockIdx.x * 64
        : Bbase + (long)b * sB + (long)blockIdx.x * 64 * ldb;

    const int warp = tid >> 5;
    const int wr = (warp >> 1) * 32;   // warp row in C tile
    const int wc = (warp & 1) * 32;    // warp col in C tile

    wmma::fragment<wmma::accumulator, 16, 16, 8, float> acc[2][2];
    #pragma unroll
    for (int i = 0; i < 2; ++i)
        #pragma unroll
        for (int j = 0; j < 2; ++j)
            wmma::fill_fragment(acc[i][j], 0.0f);

    for (int k0 = 0; k0 < K; k0 += 16) {
        // ---- stage A tile (64 rows x 16 k), convert to hi/lo tf32 ----
        #pragma unroll
        for (int p = 0; p < 2; ++p) {
            int i  = tid + p * 128;        // 0..255 float4 slots
            int r  = i >> 2;
            int c4 = (i & 3) << 2;
            float4 x = *reinterpret_cast<const float4*>(&A[(long)r * lda + k0 + c4]);
            float4 h, l;
            cvt_hl(x.x, h.x, l.x); cvt_hl(x.y, h.y, l.y);
            cvt_hl(x.z, h.z, l.z); cvt_hl(x.w, h.w, l.w);
            *reinterpret_cast<float4*>(&Ah[r * 16 + c4]) = h;
            *reinterpret_cast<float4*>(&Al[r * 16 + c4]) = l;
        }
        // ---- stage B tile ----
        #pragma unroll
        for (int p = 0; p < 2; ++p) {
            int i = tid + p * 128;
            float4 x;
            int dst;
            if (BROW) {                       // B tile: 16 k-rows x 64 n-cols
                int r  = i >> 4;
                int c4 = (i & 15) << 2;
                x = *reinterpret_cast<const float4*>(&Bm[(long)(k0 + r) * ldb + c4]);
                dst = r * 64 + c4;            // stored [16][64], ld=64
            } else {                          // B tile: 64 n-rows x 16 k-cols
                int n  = i >> 2;
                int c4 = (i & 3) << 2;
                x = *reinterpret_cast<const float4*>(&Bm[(long)n * ldb + k0 + c4]);
                dst = n * 16 + c4;            // stored [64][16], ld=16 (col-major view)
            }
            float4 h, l;
            cvt_hl(x.x, h.x, l.x); cvt_hl(x.y, h.y, l.y);
            cvt_hl(x.z, h.z, l.z); cvt_hl(x.w, h.w, l.w);
            *reinterpret_cast<float4*>(&Bh[dst]) = h;
            *reinterpret_cast<float4*>(&Bl[dst]) = l;
        }
        __syncthreads();

        #pragma unroll
        for (int kk = 0; kk < 16; kk += 8) {
            wmma::fragment<wmma::matrix_a, 16, 16, 8, wmma::precision::tf32, wmma::row_major> ah[2], al[2];
            #pragma unroll
            for (int i = 0; i < 2; ++i) {
                wmma::load_matrix_sync(ah[i], &Ah[(wr + 16 * i) * 16 + kk], 16);
                wmma::load_matrix_sync(al[i], &Al[(wr + 16 * i) * 16 + kk], 16);
            }
            if constexpr (BROW) {
                wmma::fragment<wmma::matrix_b, 16, 16, 8, wmma::precision::tf32, wmma::row_major> bh[2], bl[2];
                #pragma unroll
                for (int j = 0; j < 2; ++j) {
                    wmma::load_matrix_sync(bh[j], &Bh[kk * 64 + wc + 16 * j], 64);
                    wmma::load_matrix_sync(bl[j], &Bl[kk * 64 + wc + 16 * j], 64);
                }
                #pragma unroll
                for (int i = 0; i < 2; ++i)
                    #pragma unroll
                    for (int j = 0; j < 2; ++j) {
                        wmma::mma_sync(acc[i][j], ah[i], bh[j], acc[i][j]);
                        wmma::mma_sync(acc[i][j], ah[i], bl[j], acc[i][j]);
                        wmma::mma_sync(acc[i][j], al[i], bh[j], acc[i][j]);
                    }
            } else {
                wmma::fragment<wmma::matrix_b, 16, 16, 8, wmma::precision::tf32, wmma::col_major> bh[2], bl[2];
                #pragma unroll
                for (int j = 0; j < 2; ++j) {
                    wmma::load_matrix_sync(bh[j], &Bh[(wc + 16 * j) * 16 + kk], 16);
                    wmma::load_matrix_sync(bl[j], &Bl[(wc + 16 * j) * 16 + kk], 16);
                }
                #pragma unroll
                for (int i = 0; i < 2; ++i)
                    #pragma unroll
                    for (int j = 0; j < 2; ++j) {
                        wmma::mma_sync(acc[i][j], ah[i], bh[j], acc[i][j]);
                        wmma::mma_sync(acc[i][j], ah[i], bl[j], acc[i][j]);
                        wmma::mma_sync(acc[i][j], al[i], bh[j], acc[i][j]);
                    }
            }
        }
        __syncthreads();
    }

    // ---- epilogue: stage C through smem, then fused elementwise ----
    #pragma unroll
    for (int i = 0; i < 2; ++i)
        #pragma unroll
        for (int j = 0; j < 2; ++j)
            wmma::store_matrix_sync(&Cs[(wr + 16 * i) * 64 + wc + 16 * j],
                                    acc[i][j], 64, wmma::mem_row_major);
    __syncthreads();

    const int rowB = blockIdx.y * 64;
    const int colB = blockIdx.x * 64;
    for (int t = tid; t < 64 * 64; t += 128) {
        int r = t >> 6, c = t & 63;
        float val = Cs[t];
        long gi = (long)b * sC + (long)(rowB + r) * ldc + (colB + c);
        if (MODE == 0) {
            val += bias[colB + c];
            C1[gi] = val;
            C2[gi] = expf(val);
        } else if (MODE == 1) {
            C1[gi] = val;
            C2[gi] = expf(val);
        } else if (MODE == 2) {
            C1[gi] = logf(val);
        } else {
            int d = colB + c;
            C1[gi] = uu[gi] * S1[b * HH + d] + S2[b * HH + d] - val;
        }
    }
}

// ---------------------------------------------------------------------------
// S1[b,d] = sum_j enc[b,j,d] ; S2[b,d] = sum_j v[b,j,d]*enc[b,j,d]
// ---------------------------------------------------------------------------
__global__ void __launch_bounds__(256) colsum(
    const float* __restrict__ enc, const float* __restrict__ v,
    float* __restrict__ S1, float* __restrict__ S2)
{
    const int b = blockIdx.y;
    const int d = blockIdx.x * blockDim.x + threadIdx.x;
    const float* e  = enc + (long)b * TE * HH;
    const float* vv = v   + (long)b * TE * HH;
    float s1 = 0.f, s2 = 0.f;
    #pragma unroll 4
    for (int j = 0; j < TE; ++j) {
        float ev = e[(long)j * HH + d];
        s1 += ev;
        s2 += vv[(long)j * HH + d] * ev;
    }
    S1[b * HH + d] = s1;
    S2[b * HH + d] = s2;
}

// ---------------------------------------------------------------------------
extern "C" void kernel_launch(void* const* d_in, const int* in_sizes, int n_in,
                              void* d_out, int out_size)
{
    const float *enc = nullptr, *dec = nullptr, *W = nullptr, *bias = nullptr;
    for (int i = 0; i < n_in; ++i) {
        switch (in_sizes[i]) {
            case BSZ*TE*HH: enc  = (const float*)d_in[i]; break;
            case BSZ*TD*HH: dec  = (const float*)d_in[i]; break;
            case HH*2*HH:   W    = (const float*)d_in[i]; break;
            case HH:        bias = (const float*)d_in[i]; break;
        }
    }
    float* out = (float*)d_out;

    float *u,*Eu,*v,*Ev,*S1,*S2,*lse;
    cudaGetSymbolAddress((void**)&u,   g_u);
    cudaGetSymbolAddress((void**)&Eu,  g_Eu);
    cudaGetSymbolAddress((void**)&v,   g_v);
    cudaGetSymbolAddress((void**)&Ev,  g_Ev);
    cudaGetSymbolAddress((void**)&S1,  g_S1);
    cudaGetSymbolAddress((void**)&S2,  g_S2);
    cudaGetSymbolAddress((void**)&lse, g_lse);

    // 1) u = dec @ W_dec^T + bias ; Eu = exp(u)
    gemm_tf32<0,false><<<dim3(HH/64, TD/64, BSZ), 128>>>(
        dec, HH, (long)TD*HH,
        W,   2*HH, 0L,
        u, Eu, HH, (long)TD*HH,
        HH, bias, nullptr, nullptr, nullptr);

    // 2) v = enc @ W_enc^T ; Ev = exp(v)
    gemm_tf32<1,false><<<dim3(HH/64, TE/64, BSZ), 128>>>(
        enc, HH, (long)TE*HH,
        W + HH, 2*HH, 0L,
        v, Ev, HH, (long)TE*HH,
        HH, nullptr, nullptr, nullptr, nullptr);

    // 3) S1, S2 column sums over j
    colsum<<<dim3(HH/256, BSZ), 256>>>(enc, v, S1, S2);

    // 4) lse[b,i,j] = log( Eu[b,i,:] . Ev[b,j,:] )   (no shift needed, |u+v|<~7)
    gemm_tf32<2,false><<<dim3(TE/64, TD/64, BSZ), 128>>>(
        Eu, HH, (long)TD*HH,
        Ev, HH, (long)TE*HH,
        lse, nullptr, TE, (long)TD*TE,
        HH, nullptr, nullptr, nullptr, nullptr);

    // 5) out = u*S1 + S2 - lse @ enc
    gemm_tf32<3,true><<<dim3(HH/64, TD/64, BSZ), 128>>>(
        lse, TE, (long)TD*TE,
        enc, HH, (long)TE*HH,
        out, nullptr, HH, (long)TD*HH,
        TE, nullptr, u, S1, S2);
}

// round 5
// speedup vs baseline: 2.6328x; 2.6328x over previous
#include <cuda_runtime.h>
#include <cuda_bf16.h>
#include <mma.h>
#include <math.h>

using namespace nvcuda;

#define BSZ 8
#define TD  64
#define TE  512
#define HH  512

// Scratch (allocation-free rule: __device__ globals)
__device__ float g_u  [BSZ*TD*HH];
__device__ float g_Eu [BSZ*TD*HH];
__device__ float g_v  [BSZ*TE*HH];
__device__ float g_Ev [BSZ*TE*HH];
__device__ float g_S1 [BSZ*HH];
__device__ float g_S2 [BSZ*HH];
__device__ float g_lse[BSZ*TD*TE];
__device__ float g_pA [2*BSZ*TD*HH];   // split-K partials (reused)

__device__ __forceinline__ void cvt2(float x, __nv_bfloat16& h, __nv_bfloat16& l) {
    h = __float2bfloat16(x);
    l = __float2bfloat16(x - __bfloat162float(h));
}

// ---------------------------------------------------------------------------
// bf16 split (hi/lo, 3-mma) tensor-core GEMM.
//   BROW=false : C = A @ B^T   (A [M,K] row-major, B [N,K] row-major)
//   BROW=true  : C = A @ B     (B [K,N] row-major, transposed while staging)
// CTA tile: MT x 128, BK=32, 256 threads (8 warps: 2 rows x 4 cols).
// MODE 0: C1 = acc (+bias[col] if bias);  C2 = exp(C1)
// MODE 1: C1[ + kz*partStride ] = acc     (raw, for split-K)
// blockIdx.z = batch*SPLITK + kz.
// ---------------------------------------------------------------------------
template<int MT, int MODE, bool BROW, int SPLITK>
__global__ void __launch_bounds__(256) gemm_bf16(
    const float* __restrict__ Abase, int lda, long sA,
    const float* __restrict__ Bbase, int ldb, long sB,
    float* __restrict__ C1, float* __restrict__ C2, int ldc, long sC,
    long partStride, int K,
    const float* __restrict__ bias)
{
    constexpr int BKP = 40;                 // padded k-stride (halves)
    constexpr int WM  = MT / 2;             // warp m-extent
    constexpr int MI  = WM / 16;            // m-frags per warp
    constexpr int LOADB = (2*MT + 2*128) * BKP * 2;
    constexpr int EPIB  = 64 * 132 * 4;
    constexpr int SMEMB = LOADB > EPIB ? LOADB : EPIB;

    __shared__ alignas(16) char smem_raw[SMEMB];
    __nv_bfloat16* Ah = reinterpret_cast<__nv_bfloat16*>(smem_raw);
    __nv_bfloat16* Al = Ah + MT  * BKP;
    __nv_bfloat16* Bh = Al + MT  * BKP;
    __nv_bfloat16* Bl = Bh + 128 * BKP;
    float*         Cs = reinterpret_cast<float*>(smem_raw);

    const int tid = threadIdx.x;
    const int wid = tid >> 5;
    const int wr  = wid >> 2;               // 0..1
    const int wc  = wid & 3;                // 0..3

    const int z  = blockIdx.z;
    const int bb = z / SPLITK;
    const int kz = z % SPLITK;
    const int Ks = K / SPLITK;
    const int kbase = kz * Ks;

    const float* A  = Abase + (long)bb * sA + (long)(blockIdx.y * MT) * lda + kbase;
    const float* Bm = BROW
        ? Bbase + (long)bb * sB + (long)kbase * ldb + blockIdx.x * 128
        : Bbase + (long)bb * sB + (long)(blockIdx.x * 128) * ldb + kbase;

    wmma::fragment<wmma::accumulator, 16, 16, 16, float> acc[MI][2];
    #pragma unroll
    for (int i = 0; i < MI; ++i)
        #pragma unroll
        for (int j = 0; j < 2; ++j)
            wmma::fill_fragment(acc[i][j], 0.0f);

    const int nslab = Ks / 32;
    for (int s = 0; s < nslab; ++s) {
        const int kk = s * 32;

        // ---- stage A: MT x 32 floats -> hi/lo bf16 ----
        #pragma unroll
        for (int p = 0; p < MT/32; ++p) {
            int idx = tid + p * 256;
            int r = idx >> 3, c4 = (idx & 7) << 2;
            float4 x = *reinterpret_cast<const float4*>(&A[(long)r * lda + kk + c4]);
            __nv_bfloat16 h0,h1,h2,h3,l0,l1,l2,l3;
            cvt2(x.x,h0,l0); cvt2(x.y,h1,l1); cvt2(x.z,h2,l2); cvt2(x.w,h3,l3);
            __nv_bfloat162* dh = reinterpret_cast<__nv_bfloat162*>(&Ah[r*BKP + c4]);
            __nv_bfloat162* dl = reinterpret_cast<__nv_bfloat162*>(&Al[r*BKP + c4]);
            dh[0] = __nv_bfloat162(h0,h1); dh[1] = __nv_bfloat162(h2,h3);
            dl[0] = __nv_bfloat162(l0,l1); dl[1] = __nv_bfloat162(l2,l3);
        }
        // ---- stage B: 128 x 32 (as Bs[n][k]) ----
        if (!BROW) {
            #pragma unroll
            for (int p = 0; p < 4; ++p) {
                int idx = tid + p * 256;
                int n = idx >> 3, c4 = (idx & 7) << 2;
                float4 x = *reinterpret_cast<const float4*>(&Bm[(long)n * ldb + kk + c4]);
                __nv_bfloat16 h0,h1,h2,h3,l0,l1,l2,l3;
                cvt2(x.x,h0,l0); cvt2(x.y,h1,l1); cvt2(x.z,h2,l2); cvt2(x.w,h3,l3);
                __nv_bfloat162* dh = reinterpret_cast<__nv_bfloat162*>(&Bh[n*BKP + c4]);
                __nv_bfloat162* dl = reinterpret_cast<__nv_bfloat162*>(&Bl[n*BKP + c4]);
                dh[0] = __nv_bfloat162(h0,h1); dh[1] = __nv_bfloat162(h2,h3);
                dl[0] = __nv_bfloat162(l0,l1); dl[1] = __nv_bfloat162(l2,l3);
            }
        } else {
            // B is [K,N]; read rows of 128 n, transpose into Bs[n][k]
            #pragma unroll
            for (int p = 0; p < 4; ++p) {
                int idx = tid + p * 256;
                int r = idx >> 5, c4 = (idx & 31) << 2;
                float4 x = *reinterpret_cast<const float4*>(&Bm[(long)(kk + r) * ldb + c4]);
                __nv_bfloat16 h, l;
                cvt2(x.x,h,l); Bh[(c4+0)*BKP + r] = h; Bl[(c4+0)*BKP + r] = l;
                cvt2(x.y,h,l); Bh[(c4+1)*BKP + r] = h; Bl[(c4+1)*BKP + r] = l;
                cvt2(x.z,h,l); Bh[(c4+2)*BKP + r] = h; Bl[(c4+2)*BKP + r] = l;
                cvt2(x.w,h,l); Bh[(c4+3)*BKP + r] = h; Bl[(c4+3)*BKP + r] = l;
            }
        }
        __syncthreads();

        #pragma unroll
        for (int k2 = 0; k2 < 32; k2 += 16) {
            wmma::fragment<wmma::matrix_a, 16, 16, 16, __nv_bfloat16, wmma::row_major> ah[MI], al[MI];
            wmma::fragment<wmma::matrix_b, 16, 16, 16, __nv_bfloat16, wmma::col_major> bh[2], bl[2];
            #pragma unroll
            for (int i = 0; i < MI; ++i) {
                wmma::load_matrix_sync(ah[i], &Ah[(wr*WM + 16*i)*BKP + k2], BKP);
                wmma::load_matrix_sync(al[i], &Al[(wr*WM + 16*i)*BKP + k2], BKP);
            }
            #pragma unroll
            for (int j = 0; j < 2; ++j) {
                wmma::load_matrix_sync(bh[j], &Bh[(wc*32 + 16*j)*BKP + k2], BKP);
                wmma::load_matrix_sync(bl[j], &Bl[(wc*32 + 16*j)*BKP + k2], BKP);
            }
            #pragma unroll
            for (int i = 0; i < MI; ++i)
                #pragma unroll
                for (int j = 0; j < 2; ++j) {
                    wmma::mma_sync(acc[i][j], ah[i], bh[j], acc[i][j]);
                    wmma::mma_sync(acc[i][j], ah[i], bl[j], acc[i][j]);
                    wmma::mma_sync(acc[i][j], al[i], bh[j], acc[i][j]);
                }
        }
        __syncthreads();
    }

    // ---- epilogue: stage 64-row phases through smem ----
    #pragma unroll
    for (int ph = 0; ph < MT/64; ++ph) {
        __syncthreads();
        if (MT == 64 || wr == ph) {
            #pragma unroll
            for (int i = 0; i < MI; ++i)
                #pragma unroll
                for (int j = 0; j < 2; ++j) {
                    int lr = wr*WM + 16*i - ph*64;
                    wmma::store_matrix_sync(&Cs[lr*132 + wc*32 + 16*j],
                                            acc[i][j], 132, wmma::mem_row_major);
                }
        }
        __syncthreads();
        const int m0 = blockIdx.y * MT + ph * 64;
        const int n0 = blockIdx.x * 128;
        #pragma unroll
        for (int q = 0; q < 32; ++q) {
            int idx = tid + q * 256;
            int r = idx >> 7, c = idx & 127;
            float val = Cs[r*132 + c];
            long gi = (long)bb * sC + (long)(m0 + r) * ldc + (n0 + c);
            if (MODE == 0) {
                if (bias) val += bias[n0 + c];
                C1[gi] = val;
                C2[gi] = expf(val);
            } else {
                C1[gi + (long)kz * partStride] = val;
            }
        }
    }
}

// ---------------------------------------------------------------------------
// S1[b,d] = sum_j enc[b,j,d]; S2[b,d] = sum_j v[b,j,d]*enc[b,j,d]
// block = 256 (32 d-lanes x 8 j-groups), grid (HH/32, BSZ)
// ---------------------------------------------------------------------------
__global__ void __launch_bounds__(256) colsum(
    const float* __restrict__ enc, const float* __restrict__ v,
    float* __restrict__ S1, float* __restrict__ S2)
{
    const int b    = blockIdx.y;
    const int lane = threadIdx.x & 31;
    const int jg   = threadIdx.x >> 5;
    const int d    = blockIdx.x * 32 + lane;
    const float* e  = enc + (long)b * TE * HH + d;
    const float* vv = v   + (long)b * TE * HH + d;
    float s1 = 0.f, s2 = 0.f;
    #pragma unroll 8
    for (int j = jg; j < TE; j += 8) {
        float ev = e[(long)j * HH];
        s1 += ev;
        s2 += vv[(long)j * HH] * ev;
    }
    __shared__ float sh1[8][32], sh2[8][32];
    sh1[jg][lane] = s1; sh2[jg][lane] = s2;
    __syncthreads();
    if (jg == 0) {
        float t1 = 0.f, t2 = 0.f;
        #pragma unroll
        for (int g = 0; g < 8; ++g) { t1 += sh1[g][lane]; t2 += sh2[g][lane]; }
        S1[b*HH + d] = t1;
        S2[b*HH + d] = t2;
    }
}

// lse = log(p0 + p1)
__global__ void __launch_bounds__(256) lse_comb(
    const float* __restrict__ p0, const float* __restrict__ p1,
    float* __restrict__ lse)
{
    int i = blockIdx.x * 256 + threadIdx.x;
    lse[i] = logf(p0[i] + p1[i]);
}

// out = u*S1 + S2 - (p0 + p1)
__global__ void __launch_bounds__(256) final_comb(
    const float* __restrict__ p0, const float* __restrict__ p1,
    const float* __restrict__ u,
    const float* __restrict__ S1, const float* __restrict__ S2,
    float* __restrict__ out)
{
    int i = blockIdx.x * 256 + threadIdx.x;
    int b = i >> 15;          // / (TD*HH)
    int d = i & (HH - 1);
    out[i] = u[i] * S1[b*HH + d] + S2[b*HH + d] - (p0[i] + p1[i]);
}

// ---------------------------------------------------------------------------
extern "C" void kernel_launch(void* const* d_in, const int* in_sizes, int n_in,
                              void* d_out, int out_size)
{
    const float *enc = nullptr, *dec = nullptr, *W = nullptr, *bias = nullptr;
    for (int i = 0; i < n_in; ++i) {
        switch (in_sizes[i]) {
            case BSZ*TE*HH: enc  = (const float*)d_in[i]; break;
            case BSZ*TD*HH: dec  = (const float*)d_in[i]; break;
            case HH*2*HH:   W    = (const float*)d_in[i]; break;
            case HH:        bias = (const float*)d_in[i]; break;
        }
    }
    float* out = (float*)d_out;

    float *u,*Eu,*v,*Ev,*S1,*S2,*lse,*pA;
    cudaGetSymbolAddress((void**)&u,   g_u);
    cudaGetSymbolAddress((void**)&Eu,  g_Eu);
    cudaGetSymbolAddress((void**)&v,   g_v);
    cudaGetSymbolAddress((void**)&Ev,  g_Ev);
    cudaGetSymbolAddress((void**)&S1,  g_S1);
    cudaGetSymbolAddress((void**)&S2,  g_S2);
    cudaGetSymbolAddress((void**)&lse, g_lse);
    cudaGetSymbolAddress((void**)&pA,  g_pA);
    float* pA1 = pA + BSZ*TD*HH;

    // 1) u = dec @ W_dec^T + bias ; Eu = exp(u)   (batch folded: M = 8*64 = 512)
    gemm_bf16<64,0,false,1><<<dim3(HH/128, (BSZ*TD)/64, 1), 256>>>(
        dec, HH, 0L,  W, 2*HH, 0L,
        u, Eu, HH, 0L, 0L, HH, bias);

    // 2) v = enc @ W_enc^T ; Ev = exp(v)          (batch folded: M = 8*512 = 4096)
    gemm_bf16<128,0,false,1><<<dim3(HH/128, (BSZ*TE)/128, 1), 256>>>(
        enc, HH, 0L,  W + HH, 2*HH, 0L,
        v, Ev, HH, 0L, 0L, HH, nullptr);

    // 3) S1, S2 column sums
    colsum<<<dim3(HH/32, BSZ), 256>>>(enc, v, S1, S2);

    // 4) P[b,i,j] = Eu[b,i,:] . Ev[b,j,:]  (split-K=2 partials)
    gemm_bf16<64,1,false,2><<<dim3(TE/128, 1, BSZ*2), 256>>>(
        Eu, HH, (long)TD*HH,  Ev, HH, (long)TE*HH,
        pA, nullptr, TE, (long)TD*TE, (long)BSZ*TD*TE, HH, nullptr);

    // 5) lse = log(P0 + P1)
    lse_comb<<<(BSZ*TD*TE)/256, 256>>>(pA, pA + BSZ*TD*TE, lse);

    // 6) Q[b,i,d] = lse[b,i,:] @ enc[b,:,d]  (split-K=2 partials, reuse pA)
    gemm_bf16<64,1,true,2><<<dim3(HH/128, 1, BSZ*2), 256>>>(
        lse, TE, (long)TD*TE,  enc, HH, (long)TE*HH,
        pA, nullptr, HH, (long)TD*HH, (long)BSZ*TD*HH, TE, nullptr);

    // 7) out = u*S1 + S2 - (Q0 + Q1)
    final_comb<<<(BSZ*TD*HH)/256, 256>>>(pA, pA1, u, S1, S2, out);
}

// round 7
// speedup vs baseline: 3.5472x; 1.3473x over previous
#include <cuda_runtime.h>
#include <cuda_bf16.h>
#include <mma.h>
#include <math.h>
#include <cstdint>

using namespace nvcuda;

#define BSZ 8
#define TD  64
#define TE  512
#define HH  512

// fp32 scratch
__device__ float g_u [BSZ*TD*HH];
__device__ float g_v [BSZ*TE*HH];
__device__ float g_S1[BSZ*HH];
__device__ float g_S2[BSZ*HH];
__device__ float g_pA[2*BSZ*TD*TE];          // split-K raw partials (reused)

// bf16 hi/lo scratch
__device__ __nv_bfloat16 g_Wh [HH*2*HH],  g_Wl [HH*2*HH];
__device__ __nv_bfloat16 g_Dh [BSZ*TD*HH], g_Dl [BSZ*TD*HH];   // dec
__device__ __nv_bfloat16 g_Enh[BSZ*TE*HH], g_Enl[BSZ*TE*HH];   // enc
__device__ __nv_bfloat16 g_ETh[BSZ*HH*TE], g_ETl[BSZ*HH*TE];   // enc transposed [b,d,j]
__device__ __nv_bfloat16 g_Euh[BSZ*TD*HH], g_Eul[BSZ*TD*HH];
__device__ __nv_bfloat16 g_Evh[BSZ*TE*HH], g_Evl[BSZ*TE*HH];
__device__ __nv_bfloat16 g_Lh [BSZ*TD*TE], g_Ll [BSZ*TD*TE];   // lse hi/lo

__device__ __forceinline__ void cvt2(float x, __nv_bfloat16& h, __nv_bfloat16& l) {
    h = __float2bfloat16(x);
    l = __float2bfloat16(x - __bfloat162float(h));
}

__device__ __forceinline__ unsigned int s2u(const void* p) {
    return (unsigned int)__cvta_generic_to_shared(p);
}
__device__ __forceinline__ void cpa16(unsigned int d, const void* s) {
    asm volatile("cp.async.cg.shared.global [%0], [%1], 16;\n" :: "r"(d), "l"(s));
}
#define CP_COMMIT() asm volatile("cp.async.commit_group;\n" ::: "memory")
#define CP_WAIT0()  asm volatile("cp.async.wait_group 0;\n" ::: "memory")
#define CP_WAIT1()  asm volatile("cp.async.wait_group 1;\n" ::: "memory")

// ---------------------------------------------------------------------------
// Convert W, dec, enc to hi/lo bf16 (flat, one pass).
// ---------------------------------------------------------------------------
#define N_W   (HH*2*HH)          // 524288
#define N_D   (BSZ*TD*HH)        // 262144
#define N_E   (BSZ*TE*HH)        // 2097152
__global__ void __launch_bounds__(256) cvt_all(
    const float* __restrict__ W, const float* __restrict__ dec,
    const float* __restrict__ enc)
{
    long i = ((long)blockIdx.x * 256 + threadIdx.x) * 4;
    const float* src; __nv_bfloat16 *H, *L;
    if (i < N_W)            { src = W   + i;              H = g_Wh  + i;              L = g_Wl  + i; }
    else if (i < N_W + N_D) { long o = i - N_W;   src = dec + o; H = g_Dh + o;  L = g_Dl + o; }
    else                    { long o = i - N_W - N_D; src = enc + o; H = g_Enh + o; L = g_Enl + o; }
    float4 x = *reinterpret_cast<const float4*>(src);
    __nv_bfloat16 h0,h1,h2,h3,l0,l1,l2,l3;
    cvt2(x.x,h0,l0); cvt2(x.y,h1,l1); cvt2(x.z,h2,l2); cvt2(x.w,h3,l3);
    reinterpret_cast<__nv_bfloat162*>(H)[0] = __nv_bfloat162(h0,h1);
    reinterpret_cast<__nv_bfloat162*>(H)[1] = __nv_bfloat162(h2,h3);
    reinterpret_cast<__nv_bfloat162*>(L)[0] = __nv_bfloat162(l0,l1);
    reinterpret_cast<__nv_bfloat162*>(L)[1] = __nv_bfloat162(l2,l3);
}

// enc [b,j,d] -> encT hi/lo [b,d,j]
__global__ void encT_k(const float* __restrict__ enc)
{
    __shared__ float t[32][33];
    const int b = blockIdx.z;
    const int j0 = blockIdx.y * 32, d0 = blockIdx.x * 32;
    const float* e = enc + (long)b * TE * HH;
    #pragma unroll
    for (int p = 0; p < 4; ++p)
        t[threadIdx.y + p*8][threadIdx.x] =
            e[(long)(j0 + threadIdx.y + p*8) * HH + d0 + threadIdx.x];
    __syncthreads();
    #pragma unroll
    for (int p = 0; p < 4; ++p) {
        int d = d0 + threadIdx.y + p*8;
        float x = t[threadIdx.x][threadIdx.y + p*8];
        __nv_bfloat16 h, l; cvt2(x, h, l);
        long o = (long)b * HH * TE + (long)d * TE + j0 + threadIdx.x;
        g_ETh[o] = h; g_ETl[o] = l;
    }
}

// ---------------------------------------------------------------------------
// hi/lo bf16 GEMM, C = A @ B^T, A/B K-contiguous bf16 pairs.
// CTA tile 64 x NT, BK=32, 256 threads (8 warps 2x4), cp.async double-buffered.
// MODE 0: C1 = acc (+bias[col]); Exh/Exl = hilo(exp(C1))
// MODE 1: raw partial -> C1 + kz*partStride   (direct wmma gmem store)
// ---------------------------------------------------------------------------
template<int NT, int MODE, int SPLITK>
__global__ void __launch_bounds__(256) gemm_hl(
    const __nv_bfloat16* __restrict__ Ah, const __nv_bfloat16* __restrict__ Al, int lda, long sA,
    const __nv_bfloat16* __restrict__ Bh, const __nv_bfloat16* __restrict__ Bl, int ldb, long sB,
    float* __restrict__ C1, int ldc, long sC, long partStride,
    __nv_bfloat16* __restrict__ Exh, __nv_bfloat16* __restrict__ Exl,
    int K, const float* __restrict__ bias)
{
    constexpr int BKP = 40;
    constexpr int NJ  = NT / 64;            // b-frags per warp
    extern __shared__ __align__(16) char dsm[];
    __nv_bfloat16* As = reinterpret_cast<__nv_bfloat16*>(dsm);   // [2 stg][2 hl][64*BKP]
    __nv_bfloat16* Bs = As + 2*2*64*BKP;                         // [2 stg][2 hl][NT*BKP]
    float* Cs = reinterpret_cast<float*>(dsm);

    const int tid = threadIdx.x;
    const int wid = tid >> 5, wr = wid >> 2, wc = wid & 3;
    const int z  = blockIdx.z;
    const int bb = z / SPLITK, kz = z % SPLITK;
    const int Ks = K / SPLITK, kbase = kz * Ks, nslab = Ks / 32;

    const __nv_bfloat16* Ah0 = Ah + (long)bb*sA + (long)(blockIdx.y*64)*lda + kbase;
    const __nv_bfloat16* Al0 = Al + (long)bb*sA + (long)(blockIdx.y*64)*lda + kbase;
    const __nv_bfloat16* Bh0 = Bh + (long)bb*sB + (long)(blockIdx.x*NT)*ldb + kbase;
    const __nv_bfloat16* Bl0 = Bl + (long)bb*sB + (long)(blockIdx.x*NT)*ldb + kbase;

    const int ar = tid >> 2, ac = (tid & 3) * 8;

    wmma::fragment<wmma::accumulator, 16, 16, 16, float> acc[2][NJ];
    #pragma unroll
    for (int i = 0; i < 2; ++i)
        #pragma unroll
        for (int j = 0; j < NJ; ++j)
            wmma::fill_fragment(acc[i][j], 0.0f);

    // stage(d, k0)
    #define STAGE(d, k0) do {                                                          \
        cpa16(s2u(As + ((d)*2+0)*64*BKP + ar*BKP + ac), Ah0 + (long)ar*lda + (k0) + ac); \
        cpa16(s2u(As + ((d)*2+1)*64*BKP + ar*BKP + ac), Al0 + (long)ar*lda + (k0) + ac); \
        _Pragma("unroll")                                                              \
        for (int p = 0; p < NT/64; ++p) {                                              \
            int br = ar + p*64;                                                        \
            cpa16(s2u(Bs + ((d)*2+0)*NT*BKP + br*BKP + ac), Bh0 + (long)br*ldb + (k0) + ac); \
            cpa16(s2u(Bs + ((d)*2+1)*NT*BKP + br*BKP + ac), Bl0 + (long)br*ldb + (k0) + ac); \
        }                                                                              \
    } while (0)

    STAGE(0, 0);
    CP_COMMIT();

    for (int s = 0; s < nslab; ++s) {
        const int d = s & 1;
        if (s + 1 < nslab) {
            STAGE(1 - d, (s + 1) * 32);
            CP_COMMIT();
            CP_WAIT1();
        } else {
            CP_WAIT0();
        }
        __syncthreads();

        const __nv_bfloat16* a_h = As + (d*2+0)*64*BKP;
        const __nv_bfloat16* a_l = As + (d*2+1)*64*BKP;
        const __nv_bfloat16* b_h = Bs + (d*2+0)*NT*BKP;
        const __nv_bfloat16* b_l = Bs + (d*2+1)*NT*BKP;

        #pragma unroll
        for (int k2 = 0; k2 < 32; k2 += 16) {
            wmma::fragment<wmma::matrix_a, 16, 16, 16, __nv_bfloat16, wmma::row_major> fah[2], fal[2];
            wmma::fragment<wmma::matrix_b, 16, 16, 16, __nv_bfloat16, wmma::col_major> fbh[NJ], fbl[NJ];
            #pragma unroll
            for (int i = 0; i < 2; ++i) {
                wmma::load_matrix_sync(fah[i], a_h + (wr*32 + 16*i)*BKP + k2, BKP);
                wmma::load_matrix_sync(fal[i], a_l + (wr*32 + 16*i)*BKP + k2, BKP);
            }
            #pragma unroll
            for (int j = 0; j < NJ; ++j) {
                wmma::load_matrix_sync(fbh[j], b_h + (wc*(NT/4) + 16*j)*BKP + k2, BKP);
                wmma::load_matrix_sync(fbl[j], b_l + (wc*(NT/4) + 16*j)*BKP + k2, BKP);
            }
            #pragma unroll
            for (int i = 0; i < 2; ++i)
                #pragma unroll
                for (int j = 0; j < NJ; ++j) {
                    wmma::mma_sync(acc[i][j], fah[i], fbh[j], acc[i][j]);
                    wmma::mma_sync(acc[i][j], fah[i], fbl[j], acc[i][j]);
                    wmma::mma_sync(acc[i][j], fal[i], fbh[j], acc[i][j]);
                }
        }
        __syncthreads();
    }
    #undef STAGE

    const int m0 = blockIdx.y * 64, n0 = blockIdx.x * NT;

    if (MODE == 1) {
        float* Cp = C1 + (long)kz * partStride + (long)bb * sC;
        #pragma unroll
        for (int i = 0; i < 2; ++i)
            #pragma unroll
            for (int j = 0; j < NJ; ++j)
                wmma::store_matrix_sync(
                    &Cp[(long)(m0 + wr*32 + 16*i) * ldc + n0 + wc*(NT/4) + 16*j],
                    acc[i][j], ldc, wmma::mem_row_major);
    } else {
        #pragma unroll
        for (int i = 0; i < 2; ++i)
            #pragma unroll
            for (int j = 0; j < NJ; ++j)
                wmma::store_matrix_sync(&Cs[(wr*32 + 16*i)*(NT+4) + wc*(NT/4) + 16*j],
                                        acc[i][j], NT+4, wmma::mem_row_major);
        __syncthreads();
        #pragma unroll
        for (int q = 0; q < (64*NT)/1024; ++q) {
            int idx = (tid + q*256) * 4;
            int r = idx / NT, c = idx % NT;
            float4 vv = *reinterpret_cast<float4*>(&Cs[r*(NT+4) + c]);
            if (bias) {
                vv.x += bias[n0 + c + 0]; vv.y += bias[n0 + c + 1];
                vv.z += bias[n0 + c + 2]; vv.w += bias[n0 + c + 3];
            }
            long gi = (long)bb*sC + (long)(m0 + r)*ldc + n0 + c;
            *reinterpret_cast<float4*>(&C1[gi]) = vv;
            __nv_bfloat16 h0,h1,h2,h3,l0,l1,l2,l3;
            cvt2(expf(vv.x),h0,l0); cvt2(expf(vv.y),h1,l1);
            cvt2(expf(vv.z),h2,l2); cvt2(expf(vv.w),h3,l3);
            reinterpret_cast<__nv_bfloat162*>(&Exh[gi])[0] = __nv_bfloat162(h0,h1);
            reinterpret_cast<__nv_bfloat162*>(&Exh[gi])[1] = __nv_bfloat162(h2,h3);
            reinterpret_cast<__nv_bfloat162*>(&Exl[gi])[0] = __nv_bfloat162(l0,l1);
            reinterpret_cast<__nv_bfloat162*>(&Exl[gi])[1] = __nv_bfloat162(l2,l3);
        }
    }
}

// ---------------------------------------------------------------------------
__global__ void __launch_bounds__(256) colsum(
    const float* __restrict__ enc, const float* __restrict__ v,
    float* __restrict__ S1, float* __restrict__ S2)
{
    const int b    = blockIdx.y;
    const int lane = threadIdx.x & 31;
    const int jg   = threadIdx.x >> 5;
    const int d    = blockIdx.x * 32 + lane;
    const float* e  = enc + (long)b * TE * HH + d;
    const float* vv = v   + (long)b * TE * HH + d;
    float s1 = 0.f, s2 = 0.f;
    #pragma unroll 8
    for (int j = jg; j < TE; j += 8) {
        float ev = e[(long)j * HH];
        s1 += ev;
        s2 += vv[(long)j * HH] * ev;
    }
    __shared__ float sh1[8][32], sh2[8][32];
    sh1[jg][lane] = s1; sh2[jg][lane] = s2;
    __syncthreads();
    if (jg == 0) {
        float t1 = 0.f, t2 = 0.f;
        #pragma unroll
        for (int g = 0; g < 8; ++g) { t1 += sh1[g][lane]; t2 += sh2[g][lane]; }
        S1[b*HH + d] = t1;
        S2[b*HH + d] = t2;
    }
}

// lse = log(p0+p1) -> hi/lo bf16
__global__ void __launch_bounds__(256) lse_comb(
    const float* __restrict__ p0, const float* __restrict__ p1)
{
    int i = (blockIdx.x * 256 + threadIdx.x) * 4;
    float4 a = *reinterpret_cast<const float4*>(&p0[i]);
    float4 b = *reinterpret_cast<const float4*>(&p1[i]);
    __nv_bfloat16 h0,h1,h2,h3,l0,l1,l2,l3;
    cvt2(logf(a.x + b.x), h0,l0); cvt2(logf(a.y + b.y), h1,l1);
    cvt2(logf(a.z + b.z), h2,l2); cvt2(logf(a.w + b.w), h3,l3);
    reinterpret_cast<__nv_bfloat162*>(&g_Lh[i])[0] = __nv_bfloat162(h0,h1);
    reinterpret_cast<__nv_bfloat162*>(&g_Lh[i])[1] = __nv_bfloat162(h2,h3);
    reinterpret_cast<__nv_bfloat162*>(&g_Ll[i])[0] = __nv_bfloat162(l0,l1);
    reinterpret_cast<__nv_bfloat162*>(&g_Ll[i])[1] = __nv_bfloat162(l2,l3);
}

// out = u*S1 + S2 - (q0+q1)
__global__ void __launch_bounds__(256) final_comb(
    const float* __restrict__ q0, const float* __restrict__ q1,
    const float* __restrict__ u,
    const float* __restrict__ S1, const float* __restrict__ S2,
    float* __restrict__ out)
{
    int i = (blockIdx.x * 256 + threadIdx.x) * 4;
    int b = i >> 15;
    int d = i & (HH - 1);
    float4 a = *reinterpret_cast<const float4*>(&q0[i]);
    float4 c = *reinterpret_cast<const float4*>(&q1[i]);
    float4 uu = *reinterpret_cast<const float4*>(&u[i]);
    float4 s1 = *reinterpret_cast<const float4*>(&S1[b*HH + d]);
    float4 s2 = *reinterpret_cast<const float4*>(&S2[b*HH + d]);
    float4 o;
    o.x = uu.x*s1.x + s2.x - (a.x + c.x);
    o.y = uu.y*s1.y + s2.y - (a.y + c.y);
    o.z = uu.z*s1.z + s2.z - (a.z + c.z);
    o.w = uu.w*s1.w + s2.w - (a.w + c.w);
    *reinterpret_cast<float4*>(&out[i]) = o;
}

// ---------------------------------------------------------------------------
extern "C" void kernel_launch(void* const* d_in, const int* in_sizes, int n_in,
                              void* d_out, int out_size)
{
    const float *enc = nullptr, *dec = nullptr, *W = nullptr, *bias = nullptr;
    for (int i = 0; i < n_in; ++i) {
        switch (in_sizes[i]) {
            case BSZ*TE*HH: enc  = (const float*)d_in[i]; break;
            case BSZ*TD*HH: dec  = (const float*)d_in[i]; break;
            case HH*2*HH:   W    = (const float*)d_in[i]; break;
            case HH:        bias = (const float*)d_in[i]; break;
        }
    }
    float* out = (float*)d_out;

    float *u,*v,*S1,*S2,*pA;
    __nv_bfloat16 *Wh,*Wl,*Dh,*Dl,*Enh,*Enl,*ETh,*ETl,*Euh,*Eul,*Evh,*Evl,*Lh,*Ll;
    cudaGetSymbolAddress((void**)&u,   g_u);
    cudaGetSymbolAddress((void**)&v,   g_v);
    cudaGetSymbolAddress((void**)&S1,  g_S1);
    cudaGetSymbolAddress((void**)&S2,  g_S2);
    cudaGetSymbolAddress((void**)&pA,  g_pA);
    cudaGetSymbolAddress((void**)&Wh,  g_Wh);  cudaGetSymbolAddress((void**)&Wl,  g_Wl);
    cudaGetSymbolAddress((void**)&Dh,  g_Dh);  cudaGetSymbolAddress((void**)&Dl,  g_Dl);
    cudaGetSymbolAddress((void**)&Enh, g_Enh); cudaGetSymbolAddress((void**)&Enl, g_Enl);
    cudaGetSymbolAddress((void**)&ETh, g_ETh); cudaGetSymbolAddress((void**)&ETl, g_ETl);
    cudaGetSymbolAddress((void**)&Euh, g_Euh); cudaGetSymbolAddress((void**)&Eul, g_Eul);
    cudaGetSymbolAddress((void**)&Evh, g_Evh); cudaGetSymbolAddress((void**)&Evl, g_Evl);
    cudaGetSymbolAddress((void**)&Lh,  g_Lh);  cudaGetSymbolAddress((void**)&Ll,  g_Ll);

    constexpr int SMB64  = (64 + 64)  * 40 * 2 * 2 * 2;   // 40960
    constexpr int SMB128 = (64 + 128) * 40 * 2 * 2 * 2;   // 61440
    cudaFuncSetAttribute(gemm_hl<128,0,1>, cudaFuncAttributeMaxDynamicSharedMemorySize, SMB128);

    // 0) convert W, dec, enc to hi/lo bf16; build encT
    cvt_all<<<(N_W + N_D + N_E) / 1024, 256>>>(W, dec, enc);
    encT_k<<<dim3(HH/32, TE/32, BSZ), dim3(32, 8)>>>(enc);

    // 1) u = dec @ W_dec^T + bias ; Eu = exp(u)   (M = 512 batch-folded)
    gemm_hl<64,0,1><<<dim3(HH/64, (BSZ*TD)/64, 1), 256, SMB64>>>(
        Dh, Dl, HH, 0L,  Wh, Wl, 2*HH, 0L,
        u, HH, 0L, 0L,  Euh, Eul, HH, bias);

    // 2) v = enc @ W_enc^T ; Ev = exp(v)          (M = 4096 batch-folded)
    gemm_hl<128,0,1><<<dim3(HH/128, (BSZ*TE)/64, 1), 256, SMB128>>>(
        Enh, Enl, HH, 0L,  Wh + HH, Wl + HH, 2*HH, 0L,
        v, HH, 0L, 0L,  Evh, Evl, HH, nullptr);

    // 3) column sums
    colsum<<<dim3(HH/32, BSZ), 256>>>(enc, v, S1, S2);

    // 4) P[b,i,j] = Eu . Ev   (split-K=2 raw partials)
    gemm_hl<64,1,2><<<dim3(TE/64, 1, BSZ*2), 256, SMB64>>>(
        Euh, Eul, HH, (long)TD*HH,  Evh, Evl, HH, (long)TE*HH,
        pA, TE, (long)TD*TE, (long)BSZ*TD*TE,  nullptr, nullptr, HH, nullptr);

    // 5) lse = log(P0+P1) -> hi/lo bf16
    lse_comb<<<(BSZ*TD*TE)/1024, 256>>>(pA, pA + BSZ*TD*TE);

    // 6) Q[b,i,d] = lse @ encT^T  (split-K=2 raw partials, reuse pA)
    gemm_hl<64,1,2><<<dim3(HH/64, 1, BSZ*2), 256, SMB64>>>(
        Lh, Ll, TE, (long)TD*TE,  ETh, ETl, TE, (long)HH*TE,
        pA, HH, (long)TD*HH, (long)BSZ*TD*HH,  nullptr, nullptr, TE, nullptr);

    // 7) out = u*S1 + S2 - (Q0+Q1)
    final_comb<<<(BSZ*TD*HH)/1024, 256>>>(pA, pA + BSZ*TD*HH, u, S1, S2, out);
}